// round 5
// baseline (speedup 1.0000x reference)
#include <cuda_runtime.h>
#include <math_constants.h>

#define BB 4
#define PP 64
#define VV 32
#define DD 256

#define MARGIN 0.1f
#define L_PERM 1.0f
#define L_REG 0.1f
#define L_SIGMA 0.05f

#define NBLOCKS (BB * PP)   // 256
#define NTHREADS 512        // 8 rotation slices x 64 preds

#define ABS2MASK 0x7FFFFFFF7FFFFFFFULL

// Device scratch (no allocations allowed)
__device__ float g_costs[BB * PP * PP];
__device__ float g_reg[BB * PP];
__device__ float g_sig[BB * PP];
__device__ unsigned int g_counter = 0;

__device__ __forceinline__ unsigned long long f32x2_add(unsigned long long a,
                                                        unsigned long long b)
{
    unsigned long long d;
    asm("add.rn.f32x2 %0, %1, %2;" : "=l"(d) : "l"(a), "l"(b));
    return d;
}

__device__ __forceinline__ float hsum_f32x2(unsigned long long v)
{
    return __uint_as_float((unsigned)v) + __uint_as_float((unsigned)(v >> 32));
}

__device__ __forceinline__ unsigned long long pack2(float x, float y)
{
    return ((unsigned long long)__float_as_uint(y) << 32) |
           (unsigned long long)__float_as_uint(x);
}

// K live rotations (r = s + 8k, k < K) accumulated in registers; pred loaded
// once per v. Packed f32x2 L1 distance: add(a, -q) -> abs -> accumulate.
template <int K>
__device__ __forceinline__ float poly_min(int s, int mn, int nvg, int p,
                                          const unsigned long long* __restrict__ gtd,
                                          const unsigned long long (*__restrict__ prn)[PP])
{
    unsigned long long acc[K];
    #pragma unroll
    for (int k = 0; k < K; k++) acc[k] = 0ULL;

    #pragma unroll 2
    for (int v = 0; v < mn; v++) {
        unsigned long long q = prn[v][p];          // packed (-x, -y)
        #pragma unroll
        for (int k = 0; k < K; k++) {
            unsigned long long a = gtd[s + 8 * k + v];   // warp-uniform broadcast
            unsigned long long d = f32x2_add(a, q) & ABS2MASK;
            acc[k] = f32x2_add(acc[k], d);
        }
    }
    float best = CUDART_INF_F;
    #pragma unroll
    for (int k = 0; k < K; k++)
        if (s + 8 * k < nvg) best = fminf(best, hsum_f32x2(acc[k]));
    return best;
}

__global__ void __launch_bounds__(NTHREADS)
fused_kernel(const float* __restrict__ gt,
             const float* __restrict__ pred,
             const float* __restrict__ mu,
             const float* __restrict__ sigma,
             const int*   __restrict__ mask,
             const int*   __restrict__ cls,
             float* __restrict__ out)
{
    const int b = blockIdx.x >> 6;
    const int g = blockIdx.x & 63;
    const int tid = threadIdx.x;          // 0..511
    const int s = tid >> 6;               // rotation slice 0..7
    const int p = tid & 63;               // pred index

    __shared__ float2 gt_s[VV];
    __shared__ unsigned long long gt_dup64[2 * VV]; // packed gt[k % nvg]
    __shared__ unsigned long long predn_s[VV][PP];  // packed negated pred [v][p]
    __shared__ int    nv_s[PP];
    __shared__ float  bmin[8][PP];
    __shared__ float  red_s[16];          // 8 warps x {mu2, invsig}
    __shared__ int    is_last_s;

    // Issue cls early (independent LDG, off critical path)
    const bool is_poly = (cls[b * PP + g] == 1);

    // ---- reg/sig partials: one element per thread for tid<256 (D=256) ----
    if (tid < DD) {
        const size_t base = ((size_t)b * PP + g) * DD + tid;
        float m = mu[base];
        float sm = m * m;
        float ss = 1.0f / sigma[base];
        #pragma unroll
        for (int o = 16; o > 0; o >>= 1) {
            sm += __shfl_down_sync(0xffffffffu, sm, o);
            ss += __shfl_down_sync(0xffffffffu, ss, o);
        }
        if ((tid & 31) == 0) {
            red_s[(tid >> 5) * 2 + 0] = sm;
            red_s[(tid >> 5) * 2 + 1] = ss;
        }
    }

    // ---- load gt row for this g ----
    const float2* gt2 = (const float2*)(gt + ((size_t)b * PP + g) * VV * 2);
    if (tid < VV) gt_s[tid] = gt2[tid];

    // ---- load all pred rows of this batch, negated+packed, transposed ----
    const float2* pr2 = (const float2*)(pred + (size_t)b * PP * VV * 2);
    #pragma unroll
    for (int k = 0; k < PP * VV / NTHREADS; k++) {
        int i = tid + k * NTHREADS;
        float2 q = pr2[i];
        predn_s[i & 31][i >> 5] = pack2(-q.x, -q.y);
    }

    // ---- nv counts (one thread per pred row) ----
    if (tid < PP) {
        const int4* mrow = (const int4*)(mask + ((size_t)b * PP + tid) * VV);
        int cnt = 0;
        #pragma unroll
        for (int k = 0; k < VV / 4; k++) {
            int4 m4 = mrow[k];
            cnt += (m4.x == 0) + (m4.y == 0) + (m4.z == 0) + (m4.w == 0);
        }
        nv_s[tid] = cnt;
    }
    __syncthreads();

    const int nvg = nv_s[g];
    const int mn  = min(nvg, nv_s[p]);

    // ---- doubled packed gt table: gt_dup64[k] = gt[k % nvg], k < 64 ----
    if (tid < 2 * VV) {
        int j = tid % max(nvg, 1);
        float2 a = gt_s[j];
        gt_dup64[tid] = pack2(a.x, a.y);
    }
    __syncthreads();

    float best = CUDART_INF_F;
    if (is_poly) {
        const int kmax = (nvg > s) ? ((nvg - s + 7) >> 3) : 0;  // warp-uniform
        switch (kmax) {
        case 1: best = poly_min<1>(s, mn, nvg, p, gt_dup64, predn_s); break;
        case 2: best = poly_min<2>(s, mn, nvg, p, gt_dup64, predn_s); break;
        case 3: best = poly_min<3>(s, mn, nvg, p, gt_dup64, predn_s); break;
        case 4: best = poly_min<4>(s, mn, nvg, p, gt_dup64, predn_s); break;
        default: break;
        }
    } else if (s < 2) {
        unsigned long long acc = 0ULL;
        if (s == 0) {
            #pragma unroll 4
            for (int v = 0; v < mn; v++) {
                unsigned long long q = predn_s[v][p];
                unsigned long long d = f32x2_add(gt_dup64[v], q) & ABS2MASK;
                acc = f32x2_add(acc, d);
            }
        } else {
            #pragma unroll 4
            for (int v = 0; v < mn; v++) {
                unsigned long long q = predn_s[v][p];
                float2 a = gt_s[VV - 1 - v];
                unsigned long long d = f32x2_add(pack2(a.x, a.y), q) & ABS2MASK;
                acc = f32x2_add(acc, d);
            }
        }
        best = hsum_f32x2(acc);
    }
    bmin[s][p] = best;
    __syncthreads();

    if (tid < PP) {
        float c = CUDART_INF_F;
        #pragma unroll
        for (int k = 0; k < 8; k++) c = fminf(c, bmin[k][tid]);
        g_costs[((size_t)b * PP + g) * PP + tid] =
            c / (2.0f * (float)min(nvg, nv_s[tid]));
    }
    if (tid == 0) {
        float sm = 0.0f, ss = 0.0f;
        #pragma unroll
        for (int w = 0; w < 8; w++) { sm += red_s[w * 2]; ss += red_s[w * 2 + 1]; }
        g_reg[b * PP + g] = sm;
        g_sig[b * PP + g] = ss;
    }

    // ---- elect last block ----
    __threadfence();
    __syncthreads();
    if (tid == 0) {
        unsigned int v = atomicAdd(&g_counter, 1u);
        is_last_s = (v == NBLOCKS - 1);
    }
    __syncthreads();
    if (!is_last_s) return;

    // =========================== Phase 2 (one block) ========================
    __shared__ float diag_s[BB * PP];     // [b][i]
    __shared__ float wsum[8][3];
    __shared__ int   broken_sh[BB];

    if (tid >= 256) return;               // phase 2 uses 256 threads

    // Prefetch (overlap with diag loads)
    float rv = g_reg[tid];
    float sv = g_sig[tid];

    if (tid < BB) broken_sh[tid] = 0;
    {
        const int bb2 = tid >> 6, ii2 = tid & 63;
        diag_s[tid] = g_costs[(size_t)bb2 * PP * PP + ii2 * (PP + 1)];
    }
    __syncthreads();

    const int bb = tid >> 6;
    const int ii = tid & 63;
    const float* Cb = g_costs + (size_t)bb * PP * PP;
    const float dg = diag_s[tid];

    // Row task: max_p hinge(row) + broken-pair check
    float mrow = 0.0f;
    int brk = 0;
    const float* row = Cb + ii * PP;
    #pragma unroll 16
    for (int q = 0; q < PP; q++) {
        float c = row[q];
        if (q != ii) mrow = fmaxf(mrow, fmaxf(MARGIN - c + dg, 0.0f));
        if (c < dg) {
            if (Cb[q * PP + ii] < diag_s[(bb << 6) | q]) brk = 1;
        }
    }
    // Column task: max_g hinge(col) with diag[ii]
    float mcol = 0.0f;
    #pragma unroll 16
    for (int q = 0; q < PP; q++) {
        if (q == ii) continue;
        float c = Cb[q * PP + ii];
        mcol = fmaxf(mcol, fmaxf(MARGIN - c + dg, 0.0f));
    }
    if (brk) broken_sh[bb] = 1;

    float pv = mrow + mcol;
    #pragma unroll
    for (int o = 16; o > 0; o >>= 1) {
        pv += __shfl_down_sync(0xffffffffu, pv, o);
        rv += __shfl_down_sync(0xffffffffu, rv, o);
        sv += __shfl_down_sync(0xffffffffu, sv, o);
    }
    if ((tid & 31) == 0) {
        wsum[tid >> 5][0] = pv;
        wsum[tid >> 5][1] = rv;
        wsum[tid >> 5][2] = sv;
    }
    __syncthreads();

    if (tid < BB) {
        float perm = wsum[2 * tid][0] + wsum[2 * tid + 1][0];
        float reg  = (wsum[2 * tid][1] + wsum[2 * tid + 1][1]) / (float)PP;
        float sig  = (wsum[2 * tid][2] + wsum[2 * tid + 1][2]) / (float)(PP * DD);
        float batch = L_REG * reg + L_SIGMA * sig + L_PERM * perm;
        out[tid]          = batch;
        out[BB + tid]     = perm;
        out[2 * BB + tid] = reg;
        out[3 * BB + tid] = sig;
        out[4 * BB + tid] = broken_sh[tid] ? 1.0f : 0.0f;
    }
    if (tid == 0) g_counter = 0;   // reset for next graph replay
}

extern "C" void kernel_launch(void* const* d_in, const int* in_sizes, int n_in,
                              void* d_out, int out_size)
{
    const float* gt    = (const float*)d_in[0];
    const float* pred  = (const float*)d_in[1];
    const float* mu    = (const float*)d_in[2];
    const float* sigma = (const float*)d_in[3];
    const int*   mask  = (const int*)d_in[4];
    const int*   cls   = (const int*)d_in[5];
    float* out = (float*)d_out;

    fused_kernel<<<NBLOCKS, NTHREADS>>>(gt, pred, mu, sigma, mask, cls, out);
}

// round 6
// speedup vs baseline: 1.4095x; 1.4095x over previous
#include <cuda_runtime.h>
#include <math_constants.h>

#define BB 4
#define PP 64
#define VV 32
#define DD 256

#define MARGIN 0.1f
#define L_PERM 1.0f
#define L_REG 0.1f
#define L_SIGMA 0.05f

#define NBLOCKS (BB * PP)   // 256
#define NTHREADS 512        // 8 rotation slices x 64 preds

// Device scratch (no allocations allowed)
__device__ float g_costs[BB * PP * PP];
__device__ float g_reg[BB * PP];
__device__ float g_sig[BB * PP];
__device__ unsigned int g_counter[BB] = {0, 0, 0, 0};

__global__ void __launch_bounds__(NTHREADS)
fused_kernel(const float* __restrict__ gt,
             const float* __restrict__ pred,
             const float* __restrict__ mu,
             const float* __restrict__ sigma,
             const int*   __restrict__ mask,
             const int*   __restrict__ cls,
             float* __restrict__ out)
{
    const int b = blockIdx.x >> 6;
    const int g = blockIdx.x & 63;
    const int tid = threadIdx.x;          // 0..511
    const int s = tid >> 6;               // rotation slice 0..7
    const int p = tid & 63;               // pred index

    __shared__ float2 gt_s[VV];
    __shared__ float2 gt_dup[2 * VV];     // gt[k % nvg], branchless rotation index
    __shared__ float2 pred_s[VV][PP];     // [v][p]: conflict-free (bank = p%32)
    __shared__ int    nv_s[PP];
    __shared__ float  bmin[8][PP];
    __shared__ float  red_s[16];          // 8 warps x {mu2, invsig}
    __shared__ int    is_last_s;

    // Issue cls early (independent LDG, off critical path)
    const bool is_poly = (cls[b * PP + g] == 1);

    // ---- reg/sig partials: one element per thread for tid<256 (D=256) ----
    if (tid < DD) {
        const size_t base = ((size_t)b * PP + g) * DD + tid;
        float m = mu[base];
        float sm = m * m;
        float ss = 1.0f / sigma[base];
        #pragma unroll
        for (int o = 16; o > 0; o >>= 1) {
            sm += __shfl_down_sync(0xffffffffu, sm, o);
            ss += __shfl_down_sync(0xffffffffu, ss, o);
        }
        if ((tid & 31) == 0) {
            red_s[(tid >> 5) * 2 + 0] = sm;
            red_s[(tid >> 5) * 2 + 1] = ss;
        }
    }

    // ---- load gt row for this g ----
    const float2* gt2 = (const float2*)(gt + ((size_t)b * PP + g) * VV * 2);
    if (tid < VV) gt_s[tid] = gt2[tid];

    // ---- load all pred rows of this batch, transposed ----
    const float2* pr2 = (const float2*)(pred + (size_t)b * PP * VV * 2);
    #pragma unroll
    for (int k = 0; k < PP * VV / NTHREADS; k++) {
        int i = tid + k * NTHREADS;
        pred_s[i & 31][i >> 5] = pr2[i];
    }

    // ---- nv counts (one thread per pred row) ----
    if (tid < PP) {
        const int4* mrow = (const int4*)(mask + ((size_t)b * PP + tid) * VV);
        int cnt = 0;
        #pragma unroll
        for (int k = 0; k < VV / 4; k++) {
            int4 m4 = mrow[k];
            cnt += (m4.x == 0) + (m4.y == 0) + (m4.z == 0) + (m4.w == 0);
        }
        nv_s[tid] = cnt;
    }
    __syncthreads();

    const int nvg = nv_s[g];
    const int mn  = min(nvg, nv_s[p]);

    // ---- build doubled gt table: gt_dup[k] = gt[k % nvg] for k < 64 ----
    if (tid < 2 * VV) {
        int k = tid;
        int j = (k < nvg) ? k : (k - nvg);
        if (j >= nvg) j -= nvg;            // safe even for k >= 2*nvg (unused)
        gt_dup[k] = gt_s[j];
    }
    __syncthreads();

    float best = CUDART_INF_F;
    if (is_poly) {
        for (int r = s; r < nvg; r += 8) {
            float sx = 0.0f, sy = 0.0f;
            #pragma unroll 4
            for (int v = 0; v < mn; v++) {
                float2 a = gt_dup[r + v];      // uniform per (r,v) -> broadcast
                float2 q = pred_s[v][p];
                sx += fabsf(a.x - q.x);
                sy += fabsf(a.y - q.y);
            }
            best = fminf(best, sx + sy);
        }
    } else if (s < 2) {
        float sx = 0.0f, sy = 0.0f;
        #pragma unroll 4
        for (int v = 0; v < mn; v++) {
            float2 q = pred_s[v][p];
            float2 a = (s == 0) ? gt_s[v] : gt_s[VV - 1 - v];
            sx += fabsf(a.x - q.x);
            sy += fabsf(a.y - q.y);
        }
        best = sx + sy;
    }
    bmin[s][p] = best;
    __syncthreads();

    if (tid < PP) {
        float c = CUDART_INF_F;
        #pragma unroll
        for (int k = 0; k < 8; k++) c = fminf(c, bmin[k][tid]);
        g_costs[((size_t)b * PP + g) * PP + tid] =
            c / (2.0f * (float)min(nvg, nv_s[tid]));
    }
    if (tid == 0) {
        float sm = 0.0f, ss = 0.0f;
        #pragma unroll
        for (int w = 0; w < 8; w++) { sm += red_s[w * 2]; ss += red_s[w * 2 + 1]; }
        g_reg[b * PP + g] = sm;
        g_sig[b * PP + g] = ss;
    }

    // ---- elect last block OF THIS BATCH (per-batch counter) ----
    __threadfence();
    __syncthreads();
    if (tid == 0) {
        unsigned int v = atomicAdd(&g_counter[b], 1u);
        is_last_s = (v == PP - 1);
    }
    __syncthreads();
    if (!is_last_s) return;

    // ================= Phase 2: reduce batch b (64 threads) =================
    __shared__ float diag_s[PP];
    __shared__ float wsum[2][3];
    __shared__ int   broken_sh;

    if (tid >= PP) return;                // 64 threads remain
    __threadfence();                      // acquire: see peers' g_costs writes

    if (tid == 0) broken_sh = 0;
    const float* Cb = g_costs + (size_t)b * PP * PP;
    const int ii = tid;
    diag_s[ii] = Cb[ii * (PP + 1)];

    // Prefetch reg/sig partials for this batch
    float rv = g_reg[b * PP + tid];
    float sv = g_sig[b * PP + tid];
    __syncthreads();

    const float dg = diag_s[ii];
    const float* row = Cb + ii * PP;

    // Fused row+col hinge loop, branchless, unconditional loads (high MLP)
    float mrow = 0.0f, mcol = 0.0f;
    int brk = 0;
    #pragma unroll 8
    for (int q = 0; q < PP; q++) {
        float cr = row[q];                 // costs[ii][q]
        float cc = Cb[q * PP + ii];        // costs[q][ii]
        float dq = diag_s[q];
        if (q != ii) {
            mrow = fmaxf(mrow, fmaxf(MARGIN - cr + dg, 0.0f));
            mcol = fmaxf(mcol, fmaxf(MARGIN - cc + dg, 0.0f));
            brk |= ((cr < dg) & (cc < dq));
        }
    }
    if (brk) broken_sh = 1;

    float pv = mrow + mcol;
    #pragma unroll
    for (int o = 16; o > 0; o >>= 1) {
        pv += __shfl_down_sync(0xffffffffu, pv, o);
        rv += __shfl_down_sync(0xffffffffu, rv, o);
        sv += __shfl_down_sync(0xffffffffu, sv, o);
    }
    if ((tid & 31) == 0) {
        wsum[tid >> 5][0] = pv;
        wsum[tid >> 5][1] = rv;
        wsum[tid >> 5][2] = sv;
    }
    __syncthreads();

    if (tid == 0) {
        float perm = wsum[0][0] + wsum[1][0];
        float reg  = (wsum[0][1] + wsum[1][1]) / (float)PP;
        float sig  = (wsum[0][2] + wsum[1][2]) / (float)(PP * DD);
        float batch = L_REG * reg + L_SIGMA * sig + L_PERM * perm;
        out[b]          = batch;
        out[BB + b]     = perm;
        out[2 * BB + b] = reg;
        out[3 * BB + b] = sig;
        out[4 * BB + b] = broken_sh ? 1.0f : 0.0f;
        g_counter[b] = 0;                 // reset for next graph replay
    }
}

extern "C" void kernel_launch(void* const* d_in, const int* in_sizes, int n_in,
                              void* d_out, int out_size)
{
    const float* gt    = (const float*)d_in[0];
    const float* pred  = (const float*)d_in[1];
    const float* mu    = (const float*)d_in[2];
    const float* sigma = (const float*)d_in[3];
    const int*   mask  = (const int*)d_in[4];
    const int*   cls   = (const int*)d_in[5];
    float* out = (float*)d_out;

    fused_kernel<<<NBLOCKS, NTHREADS>>>(gt, pred, mu, sigma, mask, cls, out);
}

// round 7
// speedup vs baseline: 1.6112x; 1.1431x over previous
#include <cuda_runtime.h>
#include <math_constants.h>

#define BB 4
#define PP 64
#define VV 32
#define DD 256

#define MARGIN 0.1f
#define L_PERM 1.0f
#define L_REG 0.1f
#define L_SIGMA 0.05f

#define NBLOCKS (BB * PP)   // 256
#define NTHREADS 512        // 8 rotation slices x 64 preds

// Device scratch (no allocations allowed)
__device__ float g_costs[BB * PP * PP];
__device__ float g_reg[BB * PP];
__device__ float g_sig[BB * PP];
__device__ unsigned int g_counter[BB] = {0, 0, 0, 0};

__global__ void __launch_bounds__(NTHREADS)
fused_kernel(const float* __restrict__ gt,
             const float* __restrict__ pred,
             const float* __restrict__ mu,
             const float* __restrict__ sigma,
             const int*   __restrict__ mask,
             const int*   __restrict__ cls,
             float* __restrict__ out)
{
    const int b = blockIdx.x >> 6;
    const int g = blockIdx.x & 63;
    const int tid = threadIdx.x;          // 0..511
    const int s = tid >> 6;               // rotation slice 0..7
    const int p = tid & 63;               // pred index

    __shared__ float2 gt_s[VV];
    __shared__ float2 gt_dup[2 * VV];     // gt[k % nvg]
    __shared__ float2 pred_s[VV][PP + 1]; // padded: STS 32-way -> 2-way
    __shared__ int    nv_s[PP];
    __shared__ float  bmin[8][PP];
    __shared__ float  red_s[16];          // 8 warps x {mu2, invsig}
    __shared__ int    is_last_s;

    // Issue cls early (independent LDG, off critical path)
    const bool is_poly = (cls[b * PP + g] == 1);

    // ---- reg/sig partials: one element per thread for tid<256 (D=256) ----
    if (tid < DD) {
        const size_t base = ((size_t)b * PP + g) * DD + tid;
        float m = mu[base];
        float sm = m * m;
        float ss = 1.0f / sigma[base];
        #pragma unroll
        for (int o = 16; o > 0; o >>= 1) {
            sm += __shfl_down_sync(0xffffffffu, sm, o);
            ss += __shfl_down_sync(0xffffffffu, ss, o);
        }
        if ((tid & 31) == 0) {
            red_s[(tid >> 5) * 2 + 0] = sm;
            red_s[(tid >> 5) * 2 + 1] = ss;
        }
    }

    // ---- load gt row for this g ----
    const float2* gt2 = (const float2*)(gt + ((size_t)b * PP + g) * VV * 2);
    if (tid < VV) gt_s[tid] = gt2[tid];

    // ---- load all pred rows of this batch, transposed (padded rows) ----
    const float2* pr2 = (const float2*)(pred + (size_t)b * PP * VV * 2);
    #pragma unroll
    for (int k = 0; k < PP * VV / NTHREADS; k++) {
        int i = tid + k * NTHREADS;
        pred_s[i & 31][i >> 5] = pr2[i];
    }

    // ---- nv counts (one thread per pred row) ----
    if (tid < PP) {
        const int4* mrow = (const int4*)(mask + ((size_t)b * PP + tid) * VV);
        int cnt = 0;
        #pragma unroll
        for (int k = 0; k < VV / 4; k++) {
            int4 m4 = mrow[k];
            cnt += (m4.x == 0) + (m4.y == 0) + (m4.z == 0) + (m4.w == 0);
        }
        nv_s[tid] = cnt;
    }
    __syncthreads();

    const int nvg = nv_s[g];
    const int mn  = min(nvg, nv_s[p]);

    // ---- doubled gt table: gt_dup[k] = gt[k % max(nvg,1)] for k < 64 ----
    if (tid < 2 * VV) {
        const int nn = max(nvg, 1);
        int j = (tid < nn) ? tid : (tid - nn);
        if (j >= nn) j -= nn;
        if (j >= nn) j = 0;                // nvg tiny: clamp (unused rotations)
        gt_dup[tid] = gt_s[j];
    }
    __syncthreads();

    float best = CUDART_INF_F;
    if (is_poly) {
        // Register-blocked: 4 rotation accumulators (r = s + 8k), pred loaded
        // once per v. Invalid rotations compute garbage, masked at the end.
        float sx0 = 0.f, sy0 = 0.f, sx1 = 0.f, sy1 = 0.f;
        float sx2 = 0.f, sy2 = 0.f, sx3 = 0.f, sy3 = 0.f;
        #pragma unroll 4
        for (int v = 0; v < mn; v++) {
            float2 q = pred_s[v][p];
            float2 a0 = gt_dup[s + v];
            float2 a1 = gt_dup[s + 8 + v];
            float2 a2 = gt_dup[s + 16 + v];
            float2 a3 = gt_dup[s + 24 + v];
            sx0 += fabsf(a0.x - q.x);  sy0 += fabsf(a0.y - q.y);
            sx1 += fabsf(a1.x - q.x);  sy1 += fabsf(a1.y - q.y);
            sx2 += fabsf(a2.x - q.x);  sy2 += fabsf(a2.y - q.y);
            sx3 += fabsf(a3.x - q.x);  sy3 += fabsf(a3.y - q.y);
        }
        if (s      < nvg) best = fminf(best, sx0 + sy0);
        if (s +  8 < nvg) best = fminf(best, sx1 + sy1);
        if (s + 16 < nvg) best = fminf(best, sx2 + sy2);
        if (s + 24 < nvg) best = fminf(best, sx3 + sy3);
    } else if (s < 2) {
        float sx = 0.0f, sy = 0.0f;
        #pragma unroll 4
        for (int v = 0; v < mn; v++) {
            float2 q = pred_s[v][p];
            float2 a = (s == 0) ? gt_s[v] : gt_s[VV - 1 - v];
            sx += fabsf(a.x - q.x);
            sy += fabsf(a.y - q.y);
        }
        best = sx + sy;
    }
    bmin[s][p] = best;
    __syncthreads();

    if (tid < PP) {
        float c = CUDART_INF_F;
        #pragma unroll
        for (int k = 0; k < 8; k++) c = fminf(c, bmin[k][tid]);
        g_costs[((size_t)b * PP + g) * PP + tid] =
            c / (2.0f * (float)min(nvg, nv_s[tid]));
    }
    if (tid == 0) {
        float sm = 0.0f, ss = 0.0f;
        #pragma unroll
        for (int w = 0; w < 8; w++) { sm += red_s[w * 2]; ss += red_s[w * 2 + 1]; }
        g_reg[b * PP + g] = sm;
        g_sig[b * PP + g] = ss;
    }

    // ---- elect last block OF THIS BATCH ----
    // syncthreads (cta-scope sc fence) + single-thread gpu fence (cumulative)
    __syncthreads();
    if (tid == 0) {
        __threadfence();                   // release block's writes, one thread
        unsigned int v = atomicAdd(&g_counter[b], 1u);
        is_last_s = (v == PP - 1);
    }
    __syncthreads();
    if (!is_last_s) return;

    // ================= Phase 2: reduce batch b (64 threads) =================
    __shared__ float diag_s[PP];
    __shared__ float wsum[2][3];
    __shared__ int   broken_sh;

    if (tid >= PP) return;                // 64 threads remain
    __threadfence();                      // acquire: see peers' g_costs writes

    if (tid == 0) broken_sh = 0;
    const float* Cb = g_costs + (size_t)b * PP * PP;
    const int ii = tid;
    diag_s[ii] = Cb[ii * (PP + 1)];

    // Prefetch reg/sig partials for this batch
    float rv = g_reg[b * PP + tid];
    float sv = g_sig[b * PP + tid];
    __syncthreads();

    const float dg = diag_s[ii];
    const float* row = Cb + ii * PP;

    // Fused row+col hinge loop, branchless, unconditional loads (high MLP)
    float mrow = 0.0f, mcol = 0.0f;
    int brk = 0;
    #pragma unroll 8
    for (int q = 0; q < PP; q++) {
        float cr = row[q];                 // costs[ii][q]
        float cc = Cb[q * PP + ii];        // costs[q][ii]
        float dq = diag_s[q];
        if (q != ii) {
            mrow = fmaxf(mrow, fmaxf(MARGIN - cr + dg, 0.0f));
            mcol = fmaxf(mcol, fmaxf(MARGIN - cc + dg, 0.0f));
            brk |= ((cr < dg) & (cc < dq));
        }
    }
    if (brk) broken_sh = 1;

    float pv = mrow + mcol;
    #pragma unroll
    for (int o = 16; o > 0; o >>= 1) {
        pv += __shfl_down_sync(0xffffffffu, pv, o);
        rv += __shfl_down_sync(0xffffffffu, rv, o);
        sv += __shfl_down_sync(0xffffffffu, sv, o);
    }
    if ((tid & 31) == 0) {
        wsum[tid >> 5][0] = pv;
        wsum[tid >> 5][1] = rv;
        wsum[tid >> 5][2] = sv;
    }
    __syncthreads();

    if (tid == 0) {
        float perm = wsum[0][0] + wsum[1][0];
        float reg  = (wsum[0][1] + wsum[1][1]) / (float)PP;
        float sig  = (wsum[0][2] + wsum[1][2]) / (float)(PP * DD);
        float batch = L_REG * reg + L_SIGMA * sig + L_PERM * perm;
        out[b]          = batch;
        out[BB + b]     = perm;
        out[2 * BB + b] = reg;
        out[3 * BB + b] = sig;
        out[4 * BB + b] = broken_sh ? 1.0f : 0.0f;
        g_counter[b] = 0;                 // reset for next graph replay
    }
}

extern "C" void kernel_launch(void* const* d_in, const int* in_sizes, int n_in,
                              void* d_out, int out_size)
{
    const float* gt    = (const float*)d_in[0];
    const float* pred  = (const float*)d_in[1];
    const float* mu    = (const float*)d_in[2];
    const float* sigma = (const float*)d_in[3];
    const int*   mask  = (const int*)d_in[4];
    const int*   cls   = (const int*)d_in[5];
    float* out = (float*)d_out;

    fused_kernel<<<NBLOCKS, NTHREADS>>>(gt, pred, mu, sigma, mask, cls, out);
}

// round 8
// speedup vs baseline: 1.7648x; 1.0953x over previous
#include <cuda_runtime.h>
#include <math_constants.h>

#define BB 4
#define PP 64
#define VV 32
#define DD 256

#define MARGIN 0.1f
#define L_PERM 1.0f
#define L_REG 0.1f
#define L_SIGMA 0.05f

#define NBLOCKS (BB * PP)   // 256
#define NTHREADS 512        // 8 rotation slices x 64 preds

// Device scratch (no allocations allowed)
__device__ float g_costs[BB * PP * PP];
__device__ float g_reg[BB * PP];
__device__ float g_sig[BB * PP];
__device__ unsigned int g_counter[BB] = {0, 0, 0, 0};

__global__ void __launch_bounds__(NTHREADS)
fused_kernel(const float* __restrict__ gt,
             const float* __restrict__ pred,
             const float* __restrict__ mu,
             const float* __restrict__ sigma,
             const int*   __restrict__ mask,
             const int*   __restrict__ cls,
             float* __restrict__ out)
{
    const int b = blockIdx.x >> 6;
    const int g = blockIdx.x & 63;
    const int tid = threadIdx.x;          // 0..511
    const int s = tid >> 6;               // rotation slice 0..7
    const int p = tid & 63;               // pred index

    __shared__ float2 gt_s[VV];
    __shared__ float2 gt_dup[2 * VV];     // gt[k % nvg]
    __shared__ float2 pred_s[VV][PP + 1]; // padded: STS 32-way -> 2-way
    __shared__ int    nv_s[PP];
    __shared__ float  bmin[8][PP];
    __shared__ float  red_s[16];          // warps 0-7: mu^2, warps 8-15: 1/sigma
    __shared__ int    is_last_s;
    __shared__ float  cost_sh[PP][PP + 1];// phase-2 staging (padded)

    // Issue cls early (independent LDG, off critical path)
    const bool is_poly = (cls[b * PP + g] == 1);

    // ---- reg/sig partials: mu on threads 0-255, sigma on threads 256-511 ----
    {
        const size_t base = ((size_t)b * PP + g) * DD;
        float acc;
        if (tid < DD) {
            float m = mu[base + tid];
            acc = m * m;
        } else {
            acc = 1.0f / sigma[base + tid - DD];
        }
        #pragma unroll
        for (int o = 16; o > 0; o >>= 1)
            acc += __shfl_down_sync(0xffffffffu, acc, o);
        if ((tid & 31) == 0) red_s[tid >> 5] = acc;
    }

    // ---- load gt row for this g ----
    const float2* gt2 = (const float2*)(gt + ((size_t)b * PP + g) * VV * 2);
    if (tid < VV) gt_s[tid] = gt2[tid];

    // ---- load all pred rows of this batch, transposed (padded rows) ----
    const float2* pr2 = (const float2*)(pred + (size_t)b * PP * VV * 2);
    #pragma unroll
    for (int k = 0; k < PP * VV / NTHREADS; k++) {
        int i = tid + k * NTHREADS;
        pred_s[i & 31][i >> 5] = pr2[i];
    }

    // ---- nv counts (one thread per pred row) ----
    if (tid < PP) {
        const int4* mrow = (const int4*)(mask + ((size_t)b * PP + tid) * VV);
        int cnt = 0;
        #pragma unroll
        for (int k = 0; k < VV / 4; k++) {
            int4 m4 = mrow[k];
            cnt += (m4.x == 0) + (m4.y == 0) + (m4.z == 0) + (m4.w == 0);
        }
        nv_s[tid] = cnt;
    }
    __syncthreads();

    const int nvg = nv_s[g];
    const int mn  = min(nvg, nv_s[p]);

    // ---- doubled gt table: gt_dup[k] = gt[k % max(nvg,1)], k < 64 ----
    // Entries >= 2*nvg are garbage-but-finite; only masked accumulators see them.
    if (tid < 2 * VV) {
        const int nn = max(nvg, 1);
        int j = (tid < nn) ? tid : (tid - nn);
        if (j >= nn) j -= nn;
        if (j >= nn) j = 0;
        gt_dup[tid] = gt_s[j];
    }
    __syncthreads();

    float best = CUDART_INF_F;
    if (is_poly) {
        if (nvg <= 16) {
            // 2 accumulators cover rotations r = s, s+8 (all r < 16)
            float sx0 = 0.f, sy0 = 0.f, sx1 = 0.f, sy1 = 0.f;
            #pragma unroll 4
            for (int v = 0; v < mn; v++) {
                float2 q = pred_s[v][p];
                float2 a0 = gt_dup[s + v];
                float2 a1 = gt_dup[s + 8 + v];
                sx0 += fabsf(a0.x - q.x);  sy0 += fabsf(a0.y - q.y);
                sx1 += fabsf(a1.x - q.x);  sy1 += fabsf(a1.y - q.y);
            }
            if (s     < nvg) best = fminf(best, sx0 + sy0);
            if (s + 8 < nvg) best = fminf(best, sx1 + sy1);
        } else {
            float sx0 = 0.f, sy0 = 0.f, sx1 = 0.f, sy1 = 0.f;
            float sx2 = 0.f, sy2 = 0.f, sx3 = 0.f, sy3 = 0.f;
            #pragma unroll 4
            for (int v = 0; v < mn; v++) {
                float2 q = pred_s[v][p];
                float2 a0 = gt_dup[s + v];
                float2 a1 = gt_dup[s + 8 + v];
                float2 a2 = gt_dup[s + 16 + v];
                float2 a3 = gt_dup[s + 24 + v];
                sx0 += fabsf(a0.x - q.x);  sy0 += fabsf(a0.y - q.y);
                sx1 += fabsf(a1.x - q.x);  sy1 += fabsf(a1.y - q.y);
                sx2 += fabsf(a2.x - q.x);  sy2 += fabsf(a2.y - q.y);
                sx3 += fabsf(a3.x - q.x);  sy3 += fabsf(a3.y - q.y);
            }
            if (s      < nvg) best = fminf(best, sx0 + sy0);
            if (s +  8 < nvg) best = fminf(best, sx1 + sy1);
            if (s + 16 < nvg) best = fminf(best, sx2 + sy2);
            if (s + 24 < nvg) best = fminf(best, sx3 + sy3);
        }
    } else if (s < 2) {
        float sx = 0.0f, sy = 0.0f;
        #pragma unroll 4
        for (int v = 0; v < mn; v++) {
            float2 q = pred_s[v][p];
            float2 a = (s == 0) ? gt_s[v] : gt_s[VV - 1 - v];
            sx += fabsf(a.x - q.x);
            sy += fabsf(a.y - q.y);
        }
        best = sx + sy;
    }
    bmin[s][p] = best;
    __syncthreads();

    if (tid < PP) {
        float c = CUDART_INF_F;
        #pragma unroll
        for (int k = 0; k < 8; k++) c = fminf(c, bmin[k][tid]);
        g_costs[((size_t)b * PP + g) * PP + tid] =
            c / (2.0f * (float)min(nvg, nv_s[tid]));
    }
    if (tid == 0) {
        float sm = 0.0f, ss = 0.0f;
        #pragma unroll
        for (int w = 0; w < 8; w++) { sm += red_s[w]; ss += red_s[8 + w]; }
        g_reg[b * PP + g] = sm;
        g_sig[b * PP + g] = ss;
    }

    // ---- elect last block OF THIS BATCH ----
    __syncthreads();
    if (tid == 0) {
        __threadfence();                   // release block's writes, one thread
        unsigned int v = atomicAdd(&g_counter[b], 1u);
        is_last_s = (v == PP - 1);
    }
    __syncthreads();
    if (!is_last_s) return;

    // ================= Phase 2: reduce batch b =================
    if (tid >= 256) return;
    __threadfence();                      // acquire: see peers' g_costs writes

    // Stage cost matrix coalesced into padded smem (256 thr x 16 floats)
    const float* Cb = g_costs + (size_t)b * PP * PP;
    #pragma unroll
    for (int k = 0; k < PP * PP / 256; k++) {
        int idx = k * 256 + tid;
        cost_sh[idx >> 6][idx & 63] = Cb[idx];
    }
    // Prefetch reg/sig partials
    float rv = 0.0f, sv = 0.0f;
    if (tid < PP) {
        rv = g_reg[b * PP + tid];
        sv = g_sig[b * PP + tid];
    }
    __syncthreads();

    if (tid >= PP) return;                // 64 threads remain
    const int ii = tid;
    const float dg = cost_sh[ii][ii];

    // Fused row+col hinge loop, all conflict-free LDS
    float mrow = 0.0f, mcol = 0.0f;
    int brk = 0;
    #pragma unroll 8
    for (int q = 0; q < PP; q++) {
        float cr = cost_sh[ii][q];         // costs[ii][q]
        float cc = cost_sh[q][ii];         // costs[q][ii]
        float dq = cost_sh[q][q];          // uniform -> broadcast
        if (q != ii) {
            mrow = fmaxf(mrow, fmaxf(MARGIN - cr + dg, 0.0f));
            mcol = fmaxf(mcol, fmaxf(MARGIN - cc + dg, 0.0f));
            brk |= ((cr < dg) & (cc < dq));
        }
    }

    float pv = mrow + mcol;
    #pragma unroll
    for (int o = 16; o > 0; o >>= 1) {
        pv += __shfl_down_sync(0xffffffffu, pv, o);
        rv += __shfl_down_sync(0xffffffffu, rv, o);
        sv += __shfl_down_sync(0xffffffffu, sv, o);
    }
    brk = __any_sync(0xffffffffu, brk);

    // Combine two warps via smem
    __shared__ float wsum2[2][3];
    __shared__ int   brk2[2];
    if ((tid & 31) == 0) {
        wsum2[tid >> 5][0] = pv;
        wsum2[tid >> 5][1] = rv;
        wsum2[tid >> 5][2] = sv;
        brk2[tid >> 5] = brk;
    }
    __syncthreads();

    if (tid == 0) {
        float perm = wsum2[0][0] + wsum2[1][0];
        float reg  = (wsum2[0][1] + wsum2[1][1]) / (float)PP;
        float sig  = (wsum2[0][2] + wsum2[1][2]) / (float)(PP * DD);
        float batch = L_REG * reg + L_SIGMA * sig + L_PERM * perm;
        out[b]          = batch;
        out[BB + b]     = perm;
        out[2 * BB + b] = reg;
        out[3 * BB + b] = sig;
        out[4 * BB + b] = (brk2[0] | brk2[1]) ? 1.0f : 0.0f;
        g_counter[b] = 0;                 // reset for next graph replay
    }
}

extern "C" void kernel_launch(void* const* d_in, const int* in_sizes, int n_in,
                              void* d_out, int out_size)
{
    const float* gt    = (const float*)d_in[0];
    const float* pred  = (const float*)d_in[1];
    const float* mu    = (const float*)d_in[2];
    const float* sigma = (const float*)d_in[3];
    const int*   mask  = (const int*)d_in[4];
    const int*   cls   = (const int*)d_in[5];
    float* out = (float*)d_out;

    fused_kernel<<<NBLOCKS, NTHREADS>>>(gt, pred, mu, sigma, mask, cls, out);
}

// round 9
// speedup vs baseline: 1.7953x; 1.0172x over previous
#include <cuda_runtime.h>
#include <math_constants.h>

#define BB 4
#define PP 64
#define VV 32
#define DD 256

#define MARGIN 0.1f
#define L_PERM 1.0f
#define L_REG 0.1f
#define L_SIGMA 0.05f

#define NBLOCKS (BB * PP / 2)  // 128: one block per (b, g-pair)
#define NTHREADS 512           // 2 g-groups x (4 slices x 64 p)

// Device scratch (no allocations allowed)
__device__ float g_costs[BB * PP * PP];
__device__ float g_reg[BB * PP];
__device__ float g_sig[BB * PP];
__device__ unsigned int g_counter[BB] = {0, 0, 0, 0};

// K rotation accumulators at stride 4 (r = s + 4k), pred loaded once per v.
// Invalid rotations accumulate finite garbage, masked at the end.
template <int K>
__device__ __forceinline__ float poly_min4(int s, int mn, int nvg, int p,
                                           const float2* __restrict__ gtd,
                                           const float2 (*__restrict__ prs)[PP + 1])
{
    float sx[K], sy[K];
    #pragma unroll
    for (int k = 0; k < K; k++) { sx[k] = 0.0f; sy[k] = 0.0f; }

    #pragma unroll 2
    for (int v = 0; v < mn; v++) {
        float2 q = prs[v][p];
        #pragma unroll
        for (int k = 0; k < K; k++) {
            float2 a = gtd[s + 4 * k + v];   // warp-uniform -> broadcast
            sx[k] += fabsf(a.x - q.x);
            sy[k] += fabsf(a.y - q.y);
        }
    }
    float best = CUDART_INF_F;
    #pragma unroll
    for (int k = 0; k < K; k++)
        if (s + 4 * k < nvg) best = fminf(best, sx[k] + sy[k]);
    return best;
}

__global__ void __launch_bounds__(NTHREADS)
fused_kernel(const float* __restrict__ gt,
             const float* __restrict__ pred,
             const float* __restrict__ mu,
             const float* __restrict__ sigma,
             const int*   __restrict__ mask,
             const int*   __restrict__ cls,
             float* __restrict__ out)
{
    const int b  = blockIdx.x >> 5;        // 32 blocks per batch
    const int g0 = (blockIdx.x & 31) << 1;
    const int tid = threadIdx.x;           // 0..511
    const int gi = tid >> 8;               // which g of the pair
    const int tg = tid & 255;              // index within g-group
    const int s  = tg >> 6;                // rotation slice 0..3
    const int p  = tg & 63;                // pred index
    const int g  = g0 + gi;

    __shared__ float2 gt_s[2][VV];
    __shared__ float2 gt_dup[2][2 * VV];   // gt[k % nvg] per g
    __shared__ float2 pred_s[VV][PP + 1];  // padded, shared by both g (same b)
    __shared__ int    nv_s[PP];
    __shared__ float  bmin[2][4][PP];
    __shared__ float  red_mu[2][8], red_sg[2][8];
    __shared__ int    is_last_s;
    __shared__ float  cost_sh[PP][PP + 1]; // phase-2 staging (padded)

    // Issue cls early (L2-hot, off critical path)
    const bool is_poly = (cls[b * PP + g] == 1);

    // ---- reg/sig partials: per g-group, 256 threads, 1 mu + 1 sigma each ----
    {
        const size_t base = ((size_t)b * PP + g) * DD + tg;
        float m = mu[base];
        float sm = m * m;
        float ss = 1.0f / sigma[base];
        #pragma unroll
        for (int o = 16; o > 0; o >>= 1) {
            sm += __shfl_down_sync(0xffffffffu, sm, o);
            ss += __shfl_down_sync(0xffffffffu, ss, o);
        }
        if ((tg & 31) == 0) {
            red_mu[gi][tg >> 5] = sm;
            red_sg[gi][tg >> 5] = ss;
        }
    }

    // ---- load gt rows (one per g) ----
    if (tg < VV) {
        const float2* gt2 = (const float2*)(gt + ((size_t)b * PP + g) * VV * 2);
        gt_s[gi][tg] = gt2[tg];
    }

    // ---- load pred tile once for both g (same batch), transposed+padded ----
    const float2* pr2 = (const float2*)(pred + (size_t)b * PP * VV * 2);
    #pragma unroll
    for (int k = 0; k < PP * VV / NTHREADS; k++) {
        int i = tid + k * NTHREADS;
        pred_s[i & 31][i >> 5] = pr2[i];
    }

    // ---- nv counts (one thread per pred row) ----
    if (tid < PP) {
        const int4* mrow = (const int4*)(mask + ((size_t)b * PP + tid) * VV);
        int cnt = 0;
        #pragma unroll
        for (int k = 0; k < VV / 4; k++) {
            int4 m4 = mrow[k];
            cnt += (m4.x == 0) + (m4.y == 0) + (m4.z == 0) + (m4.w == 0);
        }
        nv_s[tid] = cnt;
    }
    __syncthreads();

    const int nvg = nv_s[g];
    const int mn  = min(nvg, nv_s[p]);

    // ---- doubled gt tables: gt_dup[gi][k] = gt[k % nvg] (valid for k<2*nvg;
    //      beyond that finite garbage, read only by masked accumulators) ----
    if (tg < 2 * VV) {
        const int nn = max(nvg, 1);
        int j = (tg < nn) ? tg : (tg - nn);
        if (j >= nn) j -= nn;
        if (j >= nn) j = 0;
        gt_dup[gi][tg] = gt_s[gi][j];
    }
    __syncthreads();

    float best = CUDART_INF_F;
    if (is_poly) {
        if (nvg <= 8)
            best = poly_min4<2>(s, mn, nvg, p, gt_dup[gi], pred_s);
        else if (nvg <= 16)
            best = poly_min4<4>(s, mn, nvg, p, gt_dup[gi], pred_s);
        else if (nvg <= 24)
            best = poly_min4<6>(s, mn, nvg, p, gt_dup[gi], pred_s);
        else
            best = poly_min4<8>(s, mn, nvg, p, gt_dup[gi], pred_s);
    } else if (s < 2) {
        float sx = 0.0f, sy = 0.0f;
        #pragma unroll 4
        for (int v = 0; v < mn; v++) {
            float2 q = pred_s[v][p];
            float2 a = (s == 0) ? gt_s[gi][v] : gt_s[gi][VV - 1 - v];
            sx += fabsf(a.x - q.x);
            sy += fabsf(a.y - q.y);
        }
        best = sx + sy;
    }
    bmin[gi][s][p] = best;
    __syncthreads();

    if (tg < PP) {
        float c = fminf(fminf(bmin[gi][0][tg], bmin[gi][1][tg]),
                        fminf(bmin[gi][2][tg], bmin[gi][3][tg]));
        g_costs[((size_t)b * PP + g) * PP + tg] =
            c / (2.0f * (float)min(nvg, nv_s[tg]));
    }
    if (tg == 0) {
        float sm = 0.0f, ss = 0.0f;
        #pragma unroll
        for (int w = 0; w < 8; w++) { sm += red_mu[gi][w]; ss += red_sg[gi][w]; }
        g_reg[b * PP + g] = sm;
        g_sig[b * PP + g] = ss;
    }

    // ---- elect last block OF THIS BATCH (32 blocks per batch) ----
    __syncthreads();
    if (tid == 0) {
        __threadfence();                   // release block's writes, one thread
        unsigned int v = atomicAdd(&g_counter[b], 1u);
        is_last_s = (v == (PP / 2) - 1);
    }
    __syncthreads();
    if (!is_last_s) return;

    // ================= Phase 2: reduce batch b =================
    if (tid >= 256) return;
    __threadfence();                      // acquire: see peers' g_costs writes

    // Stage cost matrix coalesced into padded smem (256 thr x 16 floats)
    const float* Cb = g_costs + (size_t)b * PP * PP;
    #pragma unroll
    for (int k = 0; k < PP * PP / 256; k++) {
        int idx = k * 256 + tid;
        cost_sh[idx >> 6][idx & 63] = Cb[idx];
    }
    // Prefetch reg/sig partials
    float rv = 0.0f, sv = 0.0f;
    if (tid < PP) {
        rv = g_reg[b * PP + tid];
        sv = g_sig[b * PP + tid];
    }
    __syncthreads();

    if (tid >= PP) return;                // 64 threads remain
    const int ii = tid;
    const float dg = cost_sh[ii][ii];

    // Fused row+col hinge loop, all conflict-free LDS
    float mrow = 0.0f, mcol = 0.0f;
    int brk = 0;
    #pragma unroll 8
    for (int q = 0; q < PP; q++) {
        float cr = cost_sh[ii][q];         // costs[ii][q]
        float cc = cost_sh[q][ii];         // costs[q][ii]
        float dq = cost_sh[q][q];          // uniform -> broadcast
        if (q != ii) {
            mrow = fmaxf(mrow, fmaxf(MARGIN - cr + dg, 0.0f));
            mcol = fmaxf(mcol, fmaxf(MARGIN - cc + dg, 0.0f));
            brk |= ((cr < dg) & (cc < dq));
        }
    }

    float pv = mrow + mcol;
    #pragma unroll
    for (int o = 16; o > 0; o >>= 1) {
        pv += __shfl_down_sync(0xffffffffu, pv, o);
        rv += __shfl_down_sync(0xffffffffu, rv, o);
        sv += __shfl_down_sync(0xffffffffu, sv, o);
    }
    brk = __any_sync(0xffffffffu, brk);

    __shared__ float wsum2[2][3];
    __shared__ int   brk2[2];
    if ((tid & 31) == 0) {
        wsum2[tid >> 5][0] = pv;
        wsum2[tid >> 5][1] = rv;
        wsum2[tid >> 5][2] = sv;
        brk2[tid >> 5] = brk;
    }
    __syncthreads();

    if (tid == 0) {
        float perm = wsum2[0][0] + wsum2[1][0];
        float reg  = (wsum2[0][1] + wsum2[1][1]) / (float)PP;
        float sig  = (wsum2[0][2] + wsum2[1][2]) / (float)(PP * DD);
        float batch = L_REG * reg + L_SIGMA * sig + L_PERM * perm;
        out[b]          = batch;
        out[BB + b]     = perm;
        out[2 * BB + b] = reg;
        out[3 * BB + b] = sig;
        out[4 * BB + b] = (brk2[0] | brk2[1]) ? 1.0f : 0.0f;
        g_counter[b] = 0;                 // reset for next graph replay
    }
}

extern "C" void kernel_launch(void* const* d_in, const int* in_sizes, int n_in,
                              void* d_out, int out_size)
{
    const float* gt    = (const float*)d_in[0];
    const float* pred  = (const float*)d_in[1];
    const float* mu    = (const float*)d_in[2];
    const float* sigma = (const float*)d_in[3];
    const int*   mask  = (const int*)d_in[4];
    const int*   cls   = (const int*)d_in[5];
    float* out = (float*)d_out;

    fused_kernel<<<NBLOCKS, NTHREADS>>>(gt, pred, mu, sigma, mask, cls, out);
}

// round 10
// speedup vs baseline: 1.7991x; 1.0022x over previous
#include <cuda_runtime.h>
#include <math_constants.h>

#define BB 4
#define PP 64
#define VV 32
#define DD 256

#define MARGIN 0.1f
#define L_PERM 1.0f
#define L_REG 0.1f
#define L_SIGMA 0.05f

#define NBLOCKS (BB * PP)   // 256: one block per (b, g)
#define NTHREADS 512        // 2 v-halves x 4 rotation slices x 64 preds

// Device scratch (no allocations allowed)
__device__ float g_costs[BB * PP * PP];
__device__ float g_reg[BB * PP];
__device__ float g_sig[BB * PP];
__device__ unsigned int g_counter[BB] = {0, 0, 0, 0};

// K rotation partial-accumulators at stride 4 (r = s + 4k) over v in [v0, v1).
// Results written to part[r][p] (caller passes the h-half's slab).
template <int K>
__device__ __forceinline__ void poly_part(int s, int v0, int v1, int p,
                                          const float2* __restrict__ gtd,
                                          const float2 (*__restrict__ prs)[PP + 1],
                                          float (*__restrict__ part)[PP + 1])
{
    float sx[K], sy[K];
    #pragma unroll
    for (int k = 0; k < K; k++) { sx[k] = 0.0f; sy[k] = 0.0f; }

    #pragma unroll 2
    for (int v = v0; v < v1; v++) {
        float2 q = prs[v][p];
        #pragma unroll
        for (int k = 0; k < K; k++) {
            float2 a = gtd[s + 4 * k + v];   // warp-uniform -> broadcast
            sx[k] += fabsf(a.x - q.x);
            sy[k] += fabsf(a.y - q.y);
        }
    }
    #pragma unroll
    for (int k = 0; k < K; k++)
        part[s + 4 * k][p] = sx[k] + sy[k]; // rows r >= nvg hold garbage (ignored)
}

__global__ void __launch_bounds__(NTHREADS)
fused_kernel(const float* __restrict__ gt,
             const float* __restrict__ pred,
             const float* __restrict__ mu,
             const float* __restrict__ sigma,
             const int*   __restrict__ mask,
             const int*   __restrict__ cls,
             float* __restrict__ out)
{
    const int b = blockIdx.x >> 6;
    const int g = blockIdx.x & 63;
    const int tid = threadIdx.x;           // 0..511
    const int h  = tid >> 8;               // v-half 0/1
    const int rem = tid & 255;
    const int s  = rem >> 6;               // rotation slice 0..3
    const int p  = rem & 63;               // pred index

    __shared__ float2 gt_s[VV];
    __shared__ float2 gt_dup[2 * VV];      // gt[k % nvg]
    __shared__ float2 pred_s[VV][PP + 1];  // padded
    __shared__ int    nv_s[PP];
    __shared__ float  part_s[2][VV][PP + 1]; // per-(half, rotation, p) partials
    __shared__ float  red_s[16];           // warps 0-7: mu^2, 8-15: 1/sigma
    __shared__ int    is_last_s;
    __shared__ float  cost_sh[PP][PP + 1]; // phase-2 staging (padded)

    // Issue cls early (L2-hot, off critical path)
    const bool is_poly = (cls[b * PP + g] == 1);

    // ---- reg/sig partials: mu on threads 0-255, sigma on 256-511 ----
    {
        const size_t base = ((size_t)b * PP + g) * DD;
        float acc;
        if (tid < DD) {
            float m = mu[base + tid];
            acc = m * m;
        } else {
            acc = 1.0f / sigma[base + tid - DD];
        }
        #pragma unroll
        for (int o = 16; o > 0; o >>= 1)
            acc += __shfl_down_sync(0xffffffffu, acc, o);
        if ((tid & 31) == 0) red_s[tid >> 5] = acc;
    }

    // ---- load gt row for this g ----
    if (tid < VV) {
        const float2* gt2 = (const float2*)(gt + ((size_t)b * PP + g) * VV * 2);
        gt_s[tid] = gt2[tid];
    }

    // ---- load pred tile, transposed + padded ----
    const float2* pr2 = (const float2*)(pred + (size_t)b * PP * VV * 2);
    #pragma unroll
    for (int k = 0; k < PP * VV / NTHREADS; k++) {
        int i = tid + k * NTHREADS;
        pred_s[i & 31][i >> 5] = pr2[i];
    }

    // ---- nv counts (one thread per pred row) ----
    if (tid < PP) {
        const int4* mrow = (const int4*)(mask + ((size_t)b * PP + tid) * VV);
        int cnt = 0;
        #pragma unroll
        for (int k = 0; k < VV / 4; k++) {
            int4 m4 = mrow[k];
            cnt += (m4.x == 0) + (m4.y == 0) + (m4.z == 0) + (m4.w == 0);
        }
        nv_s[tid] = cnt;
    }
    __syncthreads();

    const int nvg = nv_s[g];
    const int mn  = min(nvg, nv_s[p]);

    // ---- doubled gt table (entries >= 2*nvg finite garbage, masked later) ----
    if (tid < 2 * VV) {
        const int nn = max(nvg, 1);
        int j = (tid < nn) ? tid : (tid - nn);
        if (j >= nn) j -= nn;
        if (j >= nn) j = 0;
        gt_dup[tid] = gt_s[j];
    }
    __syncthreads();

    // ---- per-(half, rotation-slice) partial sums ----
    const int v0 = h * 16;
    const int v1 = min(mn, v0 + 16);       // empty for h=1 when mn <= 16

    if (is_poly) {
        const int kq = (nvg + 3) >> 2;     // ceil(nvg/4), block-uniform
        if (kq <= 2)      poly_part<2>(s, v0, v1, p, gt_dup, pred_s, part_s[h]);
        else if (kq <= 4) poly_part<4>(s, v0, v1, p, gt_dup, pred_s, part_s[h]);
        else if (kq <= 6) poly_part<6>(s, v0, v1, p, gt_dup, pred_s, part_s[h]);
        else              poly_part<8>(s, v0, v1, p, gt_dup, pred_s, part_s[h]);
    } else if (s < 2) {
        float sx = 0.0f, sy = 0.0f;
        #pragma unroll 2
        for (int v = v0; v < v1; v++) {
            float2 q = pred_s[v][p];
            float2 a = (s == 0) ? gt_s[v] : gt_s[VV - 1 - v];
            sx += fabsf(a.x - q.x);
            sy += fabsf(a.y - q.y);
        }
        part_s[h][s][p] = sx + sy;         // 0 when the half is empty
    }
    __syncthreads();

    // ---- combine halves, min over valid rotations, write cost row ----
    if (tid < PP) {
        const int rmax = is_poly ? nvg : 2;
        float c = CUDART_INF_F;
        for (int r = 0; r < rmax; r++)
            c = fminf(c, part_s[0][r][tid] + part_s[1][r][tid]);
        g_costs[((size_t)b * PP + g) * PP + tid] =
            c / (2.0f * (float)min(nvg, nv_s[tid]));
    }
    if (tid == 0) {
        float sm = 0.0f, ss = 0.0f;
        #pragma unroll
        for (int w = 0; w < 8; w++) { sm += red_s[w]; ss += red_s[8 + w]; }
        g_reg[b * PP + g] = sm;
        g_sig[b * PP + g] = ss;
    }

    // ---- elect last block OF THIS BATCH (64 blocks per batch) ----
    __syncthreads();
    if (tid == 0) {
        __threadfence();                   // release block's writes, one thread
        unsigned int v = atomicAdd(&g_counter[b], 1u);
        is_last_s = (v == PP - 1);
    }
    __syncthreads();
    if (!is_last_s) return;

    // ================= Phase 2: reduce batch b =================
    if (tid >= 256) return;
    __threadfence();                      // acquire: see peers' g_costs writes

    // Stage cost matrix coalesced into padded smem (256 thr x 16 floats)
    const float* Cb = g_costs + (size_t)b * PP * PP;
    #pragma unroll
    for (int k = 0; k < PP * PP / 256; k++) {
        int idx = k * 256 + tid;
        cost_sh[idx >> 6][idx & 63] = Cb[idx];
    }
    // Prefetch reg/sig partials
    float rv = 0.0f, sv = 0.0f;
    if (tid < PP) {
        rv = g_reg[b * PP + tid];
        sv = g_sig[b * PP + tid];
    }
    __syncthreads();

    if (tid >= PP) return;                // 64 threads remain
    const int ii = tid;
    const float dg = cost_sh[ii][ii];

    // Fused row+col hinge loop, all conflict-free LDS
    float mrow = 0.0f, mcol = 0.0f;
    int brk = 0;
    #pragma unroll 8
    for (int q = 0; q < PP; q++) {
        float cr = cost_sh[ii][q];         // costs[ii][q]
        float cc = cost_sh[q][ii];         // costs[q][ii]
        float dq = cost_sh[q][q];          // uniform -> broadcast
        if (q != ii) {
            mrow = fmaxf(mrow, fmaxf(MARGIN - cr + dg, 0.0f));
            mcol = fmaxf(mcol, fmaxf(MARGIN - cc + dg, 0.0f));
            brk |= ((cr < dg) & (cc < dq));
        }
    }

    float pv = mrow + mcol;
    #pragma unroll
    for (int o = 16; o > 0; o >>= 1) {
        pv += __shfl_down_sync(0xffffffffu, pv, o);
        rv += __shfl_down_sync(0xffffffffu, rv, o);
        sv += __shfl_down_sync(0xffffffffu, sv, o);
    }
    brk = __any_sync(0xffffffffu, brk);

    __shared__ float wsum2[2][3];
    __shared__ int   brk2[2];
    if ((tid & 31) == 0) {
        wsum2[tid >> 5][0] = pv;
        wsum2[tid >> 5][1] = rv;
        wsum2[tid >> 5][2] = sv;
        brk2[tid >> 5] = brk;
    }
    __syncthreads();

    if (tid == 0) {
        float perm = wsum2[0][0] + wsum2[1][0];
        float reg  = (wsum2[0][1] + wsum2[1][1]) / (float)PP;
        float sig  = (wsum2[0][2] + wsum2[1][2]) / (float)(PP * DD);
        float batch = L_REG * reg + L_SIGMA * sig + L_PERM * perm;
        out[b]          = batch;
        out[BB + b]     = perm;
        out[2 * BB + b] = reg;
        out[3 * BB + b] = sig;
        out[4 * BB + b] = (brk2[0] | brk2[1]) ? 1.0f : 0.0f;
        g_counter[b] = 0;                 // reset for next graph replay
    }
}

extern "C" void kernel_launch(void* const* d_in, const int* in_sizes, int n_in,
                              void* d_out, int out_size)
{
    const float* gt    = (const float*)d_in[0];
    const float* pred  = (const float*)d_in[1];
    const float* mu    = (const float*)d_in[2];
    const float* sigma = (const float*)d_in[3];
    const int*   mask  = (const int*)d_in[4];
    const int*   cls   = (const int*)d_in[5];
    float* out = (float*)d_out;

    fused_kernel<<<NBLOCKS, NTHREADS>>>(gt, pred, mu, sigma, mask, cls, out);
}